// round 3
// baseline (speedup 1.0000x reference)
#include <cuda_runtime.h>

// Problem shape constants (fixed by dataset: S=32, A=4, H=64).
#define S_DIM 32
#define A_DIM 4
#define F_DIM 36     // S+A
#define H_DIM 64
#define KMAX 32768
#define NACC 15      // sum_e, e*a[4], a[4], a2[4], surprise, count

__device__ float g_acc[NACC * KMAX];   // per-cluster accumulators (layout: v*K + k)
__device__ float g_ev[KMAX];           // exp(impc) if valid else 0

// ---------------- f32x2 packed-FMA helpers ----------------
__device__ __forceinline__ unsigned long long f2pack(float x, float y) {
    unsigned long long r;
    asm("mov.b64 %0, {%1, %2};" : "=l"(r) : "f"(x), "f"(y));
    return r;
}
__device__ __forceinline__ void f2unpack(unsigned long long v, float &x, float &y) {
    asm("mov.b64 {%0, %1}, %2;" : "=f"(x), "=f"(y) : "l"(v));
}
__device__ __forceinline__ unsigned long long ffma2(unsigned long long a,
                                                    unsigned long long b,
                                                    unsigned long long c) {
    unsigned long long d;
    asm("fma.rn.f32x2 %0, %1, %2, %3;" : "=l"(d) : "l"(a), "l"(b), "l"(c));
    return d;
}

// ---------------- kernel 0: zero accumulators ----------------
__global__ void zero_kernel(int total) {
    int i = blockIdx.x * 256 + threadIdx.x;
    if (i < total) g_acc[i] = 0.0f;
}

// ---------------- kernel 1: per-cell MLP + segmented accumulate ----------------
__global__ __launch_bounds__(256) void cell_kernel(
    const float* __restrict__ state, const float* __restrict__ arch,
    const float* __restrict__ energy, const float* __restrict__ phil,
    const float* __restrict__ sur, const int* __restrict__ seg,
    const float* __restrict__ W1, const float* __restrict__ b1,
    const float* __restrict__ W2, const float* __restrict__ b2,
    int N, int K)
{
    __shared__ __align__(16) float W1s[F_DIM * H_DIM];
    __shared__ __align__(16) float b1s[H_DIM];
    __shared__ float W2s[H_DIM];
    __shared__ float b2s;

    int tid = threadIdx.x;
    for (int idx = tid; idx < F_DIM * H_DIM; idx += 256) W1s[idx] = W1[idx];
    if (tid < H_DIM) { b1s[tid] = b1[tid]; W2s[tid] = W2[tid]; }
    if (tid == 0) b2s = b2[0];
    __syncthreads();

    long long i = (long long)blockIdx.x * 256 + tid;
    bool act = (i < N);

    float feats[F_DIM];
    float en = 0.f, ph = 0.f, su = 0.f;
    int sg = -1;
    if (act) {
        const float4* sp = (const float4*)(state + i * S_DIM);
        #pragma unroll
        for (int q = 0; q < 8; q++) {
            float4 v = sp[q];
            feats[q*4+0] = v.x; feats[q*4+1] = v.y;
            feats[q*4+2] = v.z; feats[q*4+3] = v.w;
        }
        float4 av = ((const float4*)arch)[i];
        feats[32] = av.x; feats[33] = av.y; feats[34] = av.z; feats[35] = av.w;
        en = energy[i]; ph = phil[i]; su = sur[i]; sg = seg[i];
    } else {
        #pragma unroll
        for (int q = 0; q < F_DIM; q++) feats[q] = 0.f;
    }

    // hidden layer: 64 accumulators as 32 packed f32x2
    unsigned long long acc[H_DIM / 2];
    const unsigned long long* b1p = (const unsigned long long*)b1s;
    #pragma unroll
    for (int j = 0; j < H_DIM / 2; j++) acc[j] = b1p[j];

    #pragma unroll
    for (int k = 0; k < F_DIM; k++) {
        unsigned long long fd = f2pack(feats[k], feats[k]);
        const ulonglong2* wr = (const ulonglong2*)(W1s + k * H_DIM);
        #pragma unroll
        for (int j = 0; j < 16; j++) {
            ulonglong2 wp = wr[j];
            acc[2*j]   = ffma2(fd, wp.x, acc[2*j]);
            acc[2*j+1] = ffma2(fd, wp.y, acc[2*j+1]);
        }
    }

    // relu + output layer
    float logit = b2s;
    #pragma unroll
    for (int j = 0; j < H_DIM / 2; j++) {
        float hx, hy;
        f2unpack(acc[j], hx, hy);
        logit += fmaxf(hx, 0.f) * W2s[2*j] + fmaxf(hy, 0.f) * W2s[2*j+1];
    }

    float base = 1.f / (1.f + __expf(-logit));
    float g   = en * ph;
    float imp = fminf(fmaxf(base * g, 0.01f), 1.0f);
    float w   = imp * g;                 // w in [0,1) -> exp needs no max-shift
    float e   = __expf(w);

    float v[NACC];
    v[0]  = e;
    v[1]  = e * feats[32]; v[2] = e * feats[33]; v[3] = e * feats[34]; v[4] = e * feats[35];
    v[5]  = feats[32]; v[6] = feats[33]; v[7] = feats[34]; v[8] = feats[35];
    v[9]  = feats[32]*feats[32]; v[10] = feats[33]*feats[33];
    v[11] = feats[34]*feats[34]; v[12] = feats[35]*feats[35];
    v[13] = su;
    v[14] = 1.0f;
    if (!act) {
        #pragma unroll
        for (int t = 0; t < NACC; t++) v[t] = 0.f;
    }

    // warp-segmented inclusive scan (seg_ids sorted -> few segments per warp)
    int lane = tid & 31;
    #pragma unroll
    for (int off = 1; off < 32; off <<= 1) {
        int sUp = __shfl_up_sync(0xffffffffu, sg, off);
        #pragma unroll
        for (int t = 0; t < NACC; t++) {
            float vu = __shfl_up_sync(0xffffffffu, v[t], off);
            if (lane >= off && sUp == sg) v[t] += vu;
        }
    }
    int sDn = __shfl_down_sync(0xffffffffu, sg, 1);
    bool tail = (lane == 31) || (sDn != sg);
    if (tail && sg >= 0) {
        #pragma unroll
        for (int t = 0; t < NACC; t++)
            atomicAdd(&g_acc[t * K + sg], v[t]);
    }
}

// ---------------- kernel 2: per-cluster stats + tiny MLP ----------------
__global__ __launch_bounds__(256) void cluster_kernel(
    const float* __restrict__ V1, const float* __restrict__ c1,
    const float* __restrict__ V2, const float* __restrict__ c2,
    float* __restrict__ dout, int K)
{
    __shared__ float V1s[7 * 32];
    __shared__ float c1s[32], V2s[32];
    __shared__ float c2s;
    int tid = threadIdx.x;
    for (int idx = tid; idx < 7 * 32; idx += 256) V1s[idx] = V1[idx];
    if (tid < 32) { c1s[tid] = c1[tid]; V2s[tid] = V2[tid]; }
    if (tid == 0) c2s = c2[0];
    __syncthreads();

    int k = blockIdx.x * 256 + tid;
    if (k >= K) return;

    float se   = g_acc[0*K + k];
    float ea[4], sa[4], sq[4];
    #pragma unroll
    for (int a = 0; a < 4; a++) {
        ea[a] = g_acc[(1+a)*K + k];
        sa[a] = g_acc[(5+a)*K + k];
        sq[a] = g_acc[(9+a)*K + k];
    }
    float ssur = g_acc[13*K + k];
    float cntf = g_acc[14*K + k];
    bool  valid = cntf > 0.f;
    float cnt = fmaxf(cntf, 1.f);

    float agg[4];
    float inv_se = valid ? (1.f / se) : 0.f;
    #pragma unroll
    for (int a = 0; a < 4; a++) agg[a] = ea[a] * inv_se;

    // softmax over archetypes
    float m = fmaxf(fmaxf(agg[0], agg[1]), fmaxf(agg[2], agg[3]));
    float ex[4], ssum = 0.f;
    #pragma unroll
    for (int a = 0; a < 4; a++) { ex[a] = __expf(agg[a] - m); ssum += ex[a]; }
    float aggregate[4];
    float inv_ss = 1.f / ssum;
    #pragma unroll
    for (int a = 0; a < 4; a++) aggregate[a] = ex[a] * inv_ss;

    // unbiased variance
    float inv_cnt = 1.f / cnt;
    float inv_dof = 1.f / fmaxf(cntf - 1.f, 1.f);
    float varm = 0.f;
    #pragma unroll
    for (int a = 0; a < 4; a++) {
        float mean = sa[a] * inv_cnt;
        float var  = (sq[a] - cntf * mean * mean) * inv_dof;
        varm += var;
    }
    varm *= 0.25f;
    float phi = 1.f - fminf(1.f, varm * 2.f);
    float coh = 1.f - varm;
    float pe  = ssur * inv_cnt;
    float integ = phi * (1.f - pe);

    // cluster MLP: 7 -> 32 -> 1
    float cf[7] = { aggregate[0], aggregate[1], aggregate[2], aggregate[3],
                    phi, coh, fminf(1.f, cntf * 0.05f) };
    float lg = c2s;
    #pragma unroll
    for (int j = 0; j < 32; j++) {
        float h = c1s[j];
        #pragma unroll
        for (int r = 0; r < 7; r++) h += cf[r] * V1s[r*32 + j];
        lg += fmaxf(h, 0.f) * V2s[j];
    }
    float basec = 1.f / (1.f + __expf(-lg));
    float impc  = fminf(fmaxf(basec * phi, 0.01f), 1.0f);

    float* row = dout + (size_t)k * 8;
    row[0] = aggregate[0]; row[1] = aggregate[1];
    row[2] = aggregate[2]; row[3] = aggregate[3];
    row[4] = phi; row[5] = coh; row[6] = pe; row[7] = integ;

    g_ev[k] = valid ? __expf(impc) : 0.f;   // impc in [0.01,1] -> exp safe
}

// ---------------- kernel 3: global reduction ----------------
__global__ __launch_bounds__(1024) void global_kernel(float* __restrict__ dout, int K)
{
    int tid = threadIdx.x;
    float Z = 0.f, S0 = 0.f, S1 = 0.f, S2 = 0.f, S3 = 0.f;
    float nv = 0.f, sp = 0.f, sc = 0.f;
    unsigned mask = 0u;

    for (int k = tid; k < K; k += blockDim.x) {
        float ev = g_ev[k];
        if (ev > 0.f) {
            const float* r = dout + (size_t)k * 8;
            float a0 = r[0], a1 = r[1], a2 = r[2], a3 = r[3];
            Z += ev;
            S0 += ev * a0; S1 += ev * a1; S2 += ev * a2; S3 += ev * a3;
            nv += 1.f; sp += r[4]; sc += r[5];
            int s = 0; float mm = a0;
            if (a1 > mm) { mm = a1; s = 1; }
            if (a2 > mm) { mm = a2; s = 2; }
            if (a3 > mm) { mm = a3; s = 3; }
            mask |= 1u << s;
        }
    }

    // warp reduce
    #pragma unroll
    for (int off = 16; off; off >>= 1) {
        Z  += __shfl_down_sync(0xffffffffu, Z,  off);
        S0 += __shfl_down_sync(0xffffffffu, S0, off);
        S1 += __shfl_down_sync(0xffffffffu, S1, off);
        S2 += __shfl_down_sync(0xffffffffu, S2, off);
        S3 += __shfl_down_sync(0xffffffffu, S3, off);
        nv += __shfl_down_sync(0xffffffffu, nv, off);
        sp += __shfl_down_sync(0xffffffffu, sp, off);
        sc += __shfl_down_sync(0xffffffffu, sc, off);
        mask |= __shfl_down_sync(0xffffffffu, mask, off);
    }

    __shared__ float sh[32][8];
    __shared__ unsigned shm[32];
    int wid = tid >> 5, lane = tid & 31;
    if (lane == 0) {
        sh[wid][0] = Z;  sh[wid][1] = S0; sh[wid][2] = S1; sh[wid][3] = S2;
        sh[wid][4] = S3; sh[wid][5] = nv; sh[wid][6] = sp; sh[wid][7] = sc;
        shm[wid] = mask;
    }
    __syncthreads();

    if (tid == 0) {
        float tZ = 0.f, t0 = 0.f, t1 = 0.f, t2 = 0.f, t3 = 0.f;
        float tnv = 0.f, tsp = 0.f, tsc = 0.f;
        unsigned tm = 0u;
        int nw = blockDim.x >> 5;
        for (int w = 0; w < nw; w++) {
            tZ += sh[w][0]; t0 += sh[w][1]; t1 += sh[w][2]; t2 += sh[w][3];
            t3 += sh[w][4]; tnv += sh[w][5]; tsp += sh[w][6]; tsc += sh[w][7];
            tm |= shm[w];
        }
        float invZ = (tZ > 0.f) ? (1.f / tZ) : 0.f;
        float g0 = t0 * invZ, g1 = t1 * invZ, g2 = t2 * invZ, g3 = t3 * invZ;
        float mx = fmaxf(fmaxf(g0, g1), fmaxf(g2, g3));
        float e0 = __expf(g0 - mx), e1 = __expf(g1 - mx);
        float e2 = __expf(g2 - mx), e3 = __expf(g3 - mx);
        float es = e0 + e1 + e2 + e3;
        float inv_es = 1.f / es;

        float nvm = fmaxf(tnv, 1.f);
        float avg_phi = tsp / nvm;
        float unique = (float)__popc(tm & 0xFu);
        float phig = fminf(1.f, avg_phi * (0.5f + 0.125f * unique));
        float vert = tsc / nvm;

        float* tl = dout + (size_t)K * 8;
        tl[0] = e0 * inv_es; tl[1] = e1 * inv_es;
        tl[2] = e2 * inv_es; tl[3] = e3 * inv_es;
        tl[4] = phig; tl[5] = vert;
    }
}

// ---------------- launch ----------------
extern "C" void kernel_launch(void* const* d_in, const int* in_sizes, int n_in,
                              void* d_out, int out_size)
{
    const float* state  = (const float*)d_in[0];
    const float* arch   = (const float*)d_in[1];
    const float* energy = (const float*)d_in[2];
    const float* phil   = (const float*)d_in[3];
    const float* sur    = (const float*)d_in[4];
    const int*   seg    = (const int*)  d_in[5];
    // d_in[6] = n_clusters scalar on device (K derived from out_size instead)
    const float* W1 = (const float*)d_in[7];
    const float* b1 = (const float*)d_in[8];
    const float* W2 = (const float*)d_in[9];
    const float* b2 = (const float*)d_in[10];
    const float* V1 = (const float*)d_in[11];
    const float* c1 = (const float*)d_in[12];
    const float* V2 = (const float*)d_in[13];
    const float* c2 = (const float*)d_in[14];

    int N = in_sizes[2];                 // energy has N elements
    int K = (out_size - 6) / 8;          // cluster_out K*8 + self_model 6

    int zt = NACC * K;
    zero_kernel<<<(zt + 255) / 256, 256>>>(zt);
    cell_kernel<<<(N + 255) / 256, 256>>>(state, arch, energy, phil, sur, seg,
                                          W1, b1, W2, b2, N, K);
    cluster_kernel<<<(K + 255) / 256, 256>>>(V1, c1, V2, c2, (float*)d_out, K);
    global_kernel<<<1, 1024>>>((float*)d_out, K);
}

// round 12
// speedup vs baseline: 1.3967x; 1.3967x over previous
#include <cuda_runtime.h>
#include <cstdint>

// Shapes fixed by dataset: S=32, A=4, F=36, H=64.
#define S_DIM 32
#define F_DIM 36
#define H_DIM 64
#define KMAX 32768
#define NACC 15
#define FROW 44            // padded feature row (floats), 16B-aligned, reduces STS conflicts

// per-cluster accumulators [NACC*K] + 16 slots of global partials at offset NACC*K
__device__ float g_acc[NACC * KMAX + 16];

// ---------------- f32x2 packed-FMA helpers ----------------
__device__ __forceinline__ unsigned long long f2pack(float x, float y) {
    unsigned long long r;
    asm("mov.b64 %0, {%1, %2};" : "=l"(r) : "f"(x), "f"(y));
    return r;
}
__device__ __forceinline__ void f2unpack(unsigned long long v, float &x, float &y) {
    asm("mov.b64 {%0, %1}, %2;" : "=f"(x), "=f"(y) : "l"(v));
}
__device__ __forceinline__ unsigned long long ffma2(unsigned long long a,
                                                    unsigned long long b,
                                                    unsigned long long c) {
    unsigned long long d;
    asm("fma.rn.f32x2 %0, %1, %2, %3;" : "=l"(d) : "l"(a), "l"(b), "l"(c));
    return d;
}

// ---------------- kernel 0: zero accumulators + global partials ----------------
__global__ void zero_kernel(int total) {
    int i = blockIdx.x * 256 + threadIdx.x;
    if (i < total) g_acc[i] = 0.0f;
}

// ---------------- kernel 1: register-weight cell MLP + segmented accumulate ----
// Each lane owns hidden units j0=2*lane, j1=2*lane+1 with weights in registers.
// Warp processes 32 cells per tile; features broadcast from SMEM.
__global__ __launch_bounds__(256, 2) void cell_kernel(
    const float* __restrict__ state, const float* __restrict__ arch,
    const float* __restrict__ energy, const float* __restrict__ phil,
    const float* __restrict__ sur, const int* __restrict__ seg,
    const float* __restrict__ W1, const float* __restrict__ b1,
    const float* __restrict__ W2, const float* __restrict__ b2,
    int N, int K)
{
    __shared__ __align__(16) float feats[8][32][FROW];

    int tid  = threadIdx.x;
    int warp = tid >> 5, lane = tid & 31;

    // per-lane weights: wreg[k] = (W1[k][2*lane], W1[k][2*lane+1]) packed
    unsigned long long wreg[F_DIM];
    #pragma unroll
    for (int k = 0; k < F_DIM; k++) {
        float2 wp = ((const float2*)(W1 + k * H_DIM))[lane];
        wreg[k] = f2pack(wp.x, wp.y);
    }
    float2 b1v = ((const float2*)b1)[lane];
    float2 W2v = ((const float2*)W2)[lane];
    float  b2v = b2[0];
    unsigned long long b1p = f2pack(b1v.x, b1v.y);

    long long nTiles = ((long long)N + 255) / 256;
    for (long long t = blockIdx.x; t < nTiles; t += gridDim.x) {
        long long cell = t * 256 + warp * 32 + lane;
        bool act = (cell < N);

        float4 a4 = make_float4(0.f, 0.f, 0.f, 0.f);
        float en = 0.f, ph = 0.f, su = 0.f;
        int sg = -1;
        float* fr = feats[warp][lane];
        if (act) {
            const float4* sp = (const float4*)(state + cell * S_DIM);
            #pragma unroll
            for (int q = 0; q < 8; q++) *(float4*)(fr + q * 4) = sp[q];
            a4 = ((const float4*)arch)[cell];
            *(float4*)(fr + 32) = a4;
            en = energy[cell]; ph = phil[cell]; su = sur[cell]; sg = seg[cell];
        } else {
            #pragma unroll
            for (int q = 0; q < 9; q++)
                *(float4*)(fr + q * 4) = make_float4(0.f, 0.f, 0.f, 0.f);
        }
        __syncwarp();

        // compute logits for all 32 cells of this warp tile
        float myLogit = 0.f;
        #pragma unroll 4
        for (int cc = 0; cc < 32; cc++) {
            const float* fb = feats[warp][cc];
            unsigned long long accA = b1p;                 // even-k chain (+bias)
            unsigned long long accB = f2pack(0.f, 0.f);    // odd-k chain
            #pragma unroll
            for (int q = 0; q < 9; q++) {
                float4 f = *(const float4*)(fb + q * 4);
                accA = ffma2(f2pack(f.x, f.x), wreg[4*q + 0], accA);
                accB = ffma2(f2pack(f.y, f.y), wreg[4*q + 1], accB);
                accA = ffma2(f2pack(f.z, f.z), wreg[4*q + 2], accA);
                accB = ffma2(f2pack(f.w, f.w), wreg[4*q + 3], accB);
            }
            float ax, ay, bx, by;
            f2unpack(accA, ax, ay);
            f2unpack(accB, bx, by);
            float h0 = ax + bx, h1 = ay + by;
            float p = fmaxf(h0, 0.f) * W2v.x + fmaxf(h1, 0.f) * W2v.y;
            #pragma unroll
            for (int off = 16; off; off >>= 1)
                p += __shfl_xor_sync(0xffffffffu, p, off);
            if (lane == cc) myLogit = p;
        }
        __syncwarp();   // done reading feats before next tile overwrites

        // per-lane tail (verified round-3 logic)
        float logit = myLogit + b2v;
        float base = 1.f / (1.f + __expf(-logit));
        float g    = en * ph;
        float imp  = fminf(fmaxf(base * g, 0.01f), 1.0f);
        float w    = imp * g;                // in [0,1): exp needs no max-shift
        float e    = __expf(w);

        float v[NACC];
        v[0]  = e;
        v[1]  = e * a4.x; v[2] = e * a4.y; v[3] = e * a4.z; v[4] = e * a4.w;
        v[5]  = a4.x; v[6] = a4.y; v[7] = a4.z; v[8] = a4.w;
        v[9]  = a4.x * a4.x; v[10] = a4.y * a4.y;
        v[11] = a4.z * a4.z; v[12] = a4.w * a4.w;
        v[13] = su;
        v[14] = 1.0f;
        if (!act) {
            #pragma unroll
            for (int q = 0; q < NACC; q++) v[q] = 0.f;
        }

        // warp-segmented inclusive scan (cells consecutive & sorted within warp)
        #pragma unroll
        for (int off = 1; off < 32; off <<= 1) {
            int sUp = __shfl_up_sync(0xffffffffu, sg, off);
            #pragma unroll
            for (int q = 0; q < NACC; q++) {
                float vu = __shfl_up_sync(0xffffffffu, v[q], off);
                if (lane >= off && sUp == sg) v[q] += vu;
            }
        }
        int sDn = __shfl_down_sync(0xffffffffu, sg, 1);
        bool tail = (lane == 31) || (sDn != sg);
        if (tail && sg >= 0) {
            #pragma unroll
            for (int q = 0; q < NACC; q++)
                atomicAdd(&g_acc[q * K + sg], v[q]);
        }
    }
}

// ---------------- kernel 2: per-cluster stats + tiny MLP + folded global partials
__global__ __launch_bounds__(256) void cluster_kernel(
    const float* __restrict__ V1, const float* __restrict__ c1,
    const float* __restrict__ V2, const float* __restrict__ c2,
    float* __restrict__ dout, int K)
{
    __shared__ float V1s[7 * 32];
    __shared__ float c1s[32], V2s[32];
    __shared__ float c2s;
    __shared__ float red[8][8];
    __shared__ unsigned redm[8];
    int tid = threadIdx.x;
    for (int idx = tid; idx < 7 * 32; idx += 256) V1s[idx] = V1[idx];
    if (tid < 32) { c1s[tid] = c1[tid]; V2s[tid] = V2[tid]; }
    if (tid == 0) c2s = c2[0];
    __syncthreads();

    int k = blockIdx.x * 256 + tid;
    bool inb = (k < K);

    float z = 0.f, s0 = 0.f, s1 = 0.f, s2 = 0.f, s3 = 0.f;
    float nv = 0.f, sp = 0.f, sc = 0.f;
    unsigned msk = 0u;

    if (inb) {
        float se = g_acc[0 * K + k];
        float ea[4], sa[4], sq[4];
        #pragma unroll
        for (int a = 0; a < 4; a++) {
            ea[a] = g_acc[(1 + a) * K + k];
            sa[a] = g_acc[(5 + a) * K + k];
            sq[a] = g_acc[(9 + a) * K + k];
        }
        float ssur = g_acc[13 * K + k];
        float cntf = g_acc[14 * K + k];
        bool  valid = cntf > 0.f;
        float cnt = fmaxf(cntf, 1.f);

        float agg[4];
        float inv_se = valid ? (1.f / se) : 0.f;
        #pragma unroll
        for (int a = 0; a < 4; a++) agg[a] = ea[a] * inv_se;

        float m = fmaxf(fmaxf(agg[0], agg[1]), fmaxf(agg[2], agg[3]));
        float ex[4], ssum = 0.f;
        #pragma unroll
        for (int a = 0; a < 4; a++) { ex[a] = __expf(agg[a] - m); ssum += ex[a]; }
        float aggregate[4];
        float inv_ss = 1.f / ssum;
        #pragma unroll
        for (int a = 0; a < 4; a++) aggregate[a] = ex[a] * inv_ss;

        float inv_cnt = 1.f / cnt;
        float inv_dof = 1.f / fmaxf(cntf - 1.f, 1.f);
        float varm = 0.f;
        #pragma unroll
        for (int a = 0; a < 4; a++) {
            float mean = sa[a] * inv_cnt;
            varm += (sq[a] - cntf * mean * mean) * inv_dof;
        }
        varm *= 0.25f;
        float phi = 1.f - fminf(1.f, varm * 2.f);
        float coh = 1.f - varm;
        float pe  = ssur * inv_cnt;
        float integ = phi * (1.f - pe);

        float cf[7] = { aggregate[0], aggregate[1], aggregate[2], aggregate[3],
                        phi, coh, fminf(1.f, cntf * 0.05f) };
        float lg = c2s;
        #pragma unroll
        for (int j = 0; j < 32; j++) {
            float h = c1s[j];
            #pragma unroll
            for (int r = 0; r < 7; r++) h += cf[r] * V1s[r * 32 + j];
            lg += fmaxf(h, 0.f) * V2s[j];
        }
        float basec = 1.f / (1.f + __expf(-lg));
        float impc  = fminf(fmaxf(basec * phi, 0.01f), 1.0f);

        float* row = dout + (size_t)k * 8;
        row[0] = aggregate[0]; row[1] = aggregate[1];
        row[2] = aggregate[2]; row[3] = aggregate[3];
        row[4] = phi; row[5] = coh; row[6] = pe; row[7] = integ;

        if (valid) {
            float ev = __expf(impc);
            z = ev;
            s0 = ev * aggregate[0]; s1 = ev * aggregate[1];
            s2 = ev * aggregate[2]; s3 = ev * aggregate[3];
            nv = 1.f; sp = phi; sc = coh;
            int s = 0; float mm = aggregate[0];
            if (aggregate[1] > mm) { mm = aggregate[1]; s = 1; }
            if (aggregate[2] > mm) { mm = aggregate[2]; s = 2; }
            if (aggregate[3] > mm) { mm = aggregate[3]; s = 3; }
            msk = 1u << s;
        }
    }

    // block-reduce 8 floats + mask, then atomics into global partials
    #pragma unroll
    for (int off = 16; off; off >>= 1) {
        z  += __shfl_down_sync(0xffffffffu, z,  off);
        s0 += __shfl_down_sync(0xffffffffu, s0, off);
        s1 += __shfl_down_sync(0xffffffffu, s1, off);
        s2 += __shfl_down_sync(0xffffffffu, s2, off);
        s3 += __shfl_down_sync(0xffffffffu, s3, off);
        nv += __shfl_down_sync(0xffffffffu, nv, off);
        sp += __shfl_down_sync(0xffffffffu, sp, off);
        sc += __shfl_down_sync(0xffffffffu, sc, off);
        msk |= __shfl_down_sync(0xffffffffu, msk, off);
    }
    int wid = tid >> 5, lane = tid & 31;
    if (lane == 0) {
        red[wid][0] = z;  red[wid][1] = s0; red[wid][2] = s1; red[wid][3] = s2;
        red[wid][4] = s3; red[wid][5] = nv; red[wid][6] = sp; red[wid][7] = sc;
        redm[wid] = msk;
    }
    __syncthreads();
    if (tid == 0) {
        float t[8] = {0, 0, 0, 0, 0, 0, 0, 0};
        unsigned tm = 0u;
        #pragma unroll
        for (int w = 0; w < 8; w++) {
            #pragma unroll
            for (int q = 0; q < 8; q++) t[q] += red[w][q];
            tm |= redm[w];
        }
        float* P = g_acc + (size_t)NACC * K;
        #pragma unroll
        for (int q = 0; q < 8; q++) atomicAdd(&P[q], t[q]);
        atomicOr((unsigned*)(P + 8), tm);
    }
}

// ---------------- kernel 3: tiny final reduction (6 trailing outputs) --------
__global__ void final_kernel(float* __restrict__ dout, int K)
{
    if (threadIdx.x == 0) {
        const float* P = g_acc + (size_t)NACC * K;
        float Z = P[0], S0 = P[1], S1 = P[2], S2 = P[3], S3 = P[4];
        float nv = P[5], sp = P[6], sc = P[7];
        unsigned tm = *(const unsigned*)(P + 8);

        float invZ = (Z > 0.f) ? (1.f / Z) : 0.f;
        float g0 = S0 * invZ, g1 = S1 * invZ, g2 = S2 * invZ, g3 = S3 * invZ;
        float mx = fmaxf(fmaxf(g0, g1), fmaxf(g2, g3));
        float e0 = __expf(g0 - mx), e1 = __expf(g1 - mx);
        float e2 = __expf(g2 - mx), e3 = __expf(g3 - mx);
        float inv_es = 1.f / (e0 + e1 + e2 + e3);

        float nvm = fmaxf(nv, 1.f);
        float avg_phi = sp / nvm;
        float unique = (float)__popc(tm & 0xFu);
        float phig = fminf(1.f, avg_phi * (0.5f + 0.125f * unique));
        float vert = sc / nvm;

        float* tl = dout + (size_t)K * 8;
        tl[0] = e0 * inv_es; tl[1] = e1 * inv_es;
        tl[2] = e2 * inv_es; tl[3] = e3 * inv_es;
        tl[4] = phig; tl[5] = vert;
    }
}

// ---------------- launch ----------------
extern "C" void kernel_launch(void* const* d_in, const int* in_sizes, int n_in,
                              void* d_out, int out_size)
{
    const float* state  = (const float*)d_in[0];
    const float* arch   = (const float*)d_in[1];
    const float* energy = (const float*)d_in[2];
    const float* phil   = (const float*)d_in[3];
    const float* sur    = (const float*)d_in[4];
    const int*   seg    = (const int*)  d_in[5];
    // d_in[6] = n_clusters scalar (K derived from out_size)
    const float* W1 = (const float*)d_in[7];
    const float* b1 = (const float*)d_in[8];
    const float* W2 = (const float*)d_in[9];
    const float* b2 = (const float*)d_in[10];
    const float* V1 = (const float*)d_in[11];
    const float* c1 = (const float*)d_in[12];
    const float* V2 = (const float*)d_in[13];
    const float* c2 = (const float*)d_in[14];

    int N = in_sizes[2];
    int K = (out_size - 6) / 8;

    int zt = NACC * K + 16;
    zero_kernel<<<(zt + 255) / 256, 256>>>(zt);

    long long nTiles = ((long long)N + 255) / 256;
    int grid = (int)(nTiles < 296 ? nTiles : 296);   // 2 CTAs/SM resident
    cell_kernel<<<grid, 256>>>(state, arch, energy, phil, sur, seg,
                               W1, b1, W2, b2, N, K);
    cluster_kernel<<<(K + 255) / 256, 256>>>(V1, c1, V2, c2, (float*)d_out, K);
    final_kernel<<<1, 32>>>((float*)d_out, K);
}